// round 11
// baseline (speedup 1.0000x reference)
#include <cuda_runtime.h>
#include <cuda_bf16.h>
#include <cstdint>

// Problem constants
#define HH   16
#define DD   64
#define BB   2
#define NN   1024
#define MM   2048
#define CC   1024
#define KVD  768
#define QK_SCALE 0.125f   // 64^-0.5

// ---------------------------------------------------------------------------
// Scratch (allocation-free: __device__ globals).
// NOTE: these are ONLY referenced from device code — taking their address in
// host code yields the host shadow symbol (the R9/R10 bug).
// ---------------------------------------------------------------------------
__device__ __align__(16) __nv_bfloat16 g_qhh[BB*HH*NN*DD];  // scaled Q hi [b,h,n,d]
__device__ __align__(16) __nv_bfloat16 g_qhl[BB*HH*NN*DD];  // scaled Q lo
__device__ __align__(16) __nv_bfloat16 g_kh [BB*HH*MM*DD];  // K hi [b,h,m,d]
__device__ __align__(16) __nv_bfloat16 g_kl [BB*HH*MM*DD];  // K lo
__device__ __align__(16) __nv_bfloat16 g_vh [BB*HH*DD*MM];  // V hi TRANSPOSED [b,h,d,m]
__device__ __align__(16) __nv_bfloat16 g_vl [BB*HH*DD*MM];  // V lo TRANSPOSED
__device__ __align__(16) __nv_bfloat16 g_q_h [BB*NN*CC];    // pre-split GEMM operands
__device__ __align__(16) __nv_bfloat16 g_q_l [BB*NN*CC];
__device__ __align__(16) __nv_bfloat16 g_kv_h[BB*MM*KVD];
__device__ __align__(16) __nv_bfloat16 g_kv_l[BB*MM*KVD];
__device__ __align__(16) __nv_bfloat16 g_wq_h[CC*CC];
__device__ __align__(16) __nv_bfloat16 g_wq_l[CC*CC];
__device__ __align__(16) __nv_bfloat16 g_wkv_h[2*CC*KVD];
__device__ __align__(16) __nv_bfloat16 g_wkv_l[2*CC*KVD];
__device__ __align__(16) __nv_bfloat16 g_wp_h[CC*CC];
__device__ __align__(16) __nv_bfloat16 g_wp_l[CC*CC];
__device__ __align__(16) __nv_bfloat16 g_xh[BB*NN*CC];      // attn out hi [b,n,h*D+d]
__device__ __align__(16) __nv_bfloat16 g_xl[BB*NN*CC];      // attn out lo
__device__ __align__(16) float g_maskbias[BB*MM];           // 0 or -1e30

// ---------------------------------------------------------------------------
// Helpers
// ---------------------------------------------------------------------------
__device__ __forceinline__ void cpasync16(void* smem, const void* gmem) {
    unsigned s = (unsigned)__cvta_generic_to_shared(smem);
    asm volatile("cp.async.ca.shared.global [%0], [%1], 16;" :: "r"(s), "l"(gmem));
}
#define CP_COMMIT() asm volatile("cp.async.commit_group;" ::: "memory")
#define CP_WAIT0()  asm volatile("cp.async.wait_group 0;" ::: "memory")

// Warp-level HMMA: D(16x8,f32) += A(16x16,bf16 row) * B(16x8,bf16 col)
__device__ __forceinline__ void mma16816(float* d, const unsigned* a, const unsigned* b)
{
    asm volatile(
        "mma.sync.aligned.m16n8k16.row.col.f32.bf16.bf16.f32 "
        "{%0,%1,%2,%3}, {%4,%5,%6,%7}, {%8,%9}, {%0,%1,%2,%3};"
        : "+f"(d[0]), "+f"(d[1]), "+f"(d[2]), "+f"(d[3])
        : "r"(a[0]), "r"(a[1]), "r"(a[2]), "r"(a[3]), "r"(b[0]), "r"(b[1]));
}

// fp32x2 -> bf16x2 hi/lo
__device__ __forceinline__ void split2(float x, float y,
                                       __nv_bfloat162& h, __nv_bfloat162& l)
{
    h = __floats2bfloat162_rn(x, y);
    float rx = x - __low2float(h);
    float ry = y - __high2float(h);
    l = __floats2bfloat162_rn(rx, ry);
}

// ---------------------------------------------------------------------------
// Prep: elementwise fp32 -> bf16 hi/lo split. Destination globals selected
// IN DEVICE CODE by SEL (0:q 1:kv 2:Wq 3:Wkv 4:Wproj).
// ---------------------------------------------------------------------------
template<int SEL>
__global__ void split_arr(const float4* __restrict__ in, int n4)
{
    __nv_bfloat162* hi;
    __nv_bfloat162* lo;
    if      (SEL == 0) { hi = (__nv_bfloat162*)g_q_h;  lo = (__nv_bfloat162*)g_q_l;  }
    else if (SEL == 1) { hi = (__nv_bfloat162*)g_kv_h; lo = (__nv_bfloat162*)g_kv_l; }
    else if (SEL == 2) { hi = (__nv_bfloat162*)g_wq_h; lo = (__nv_bfloat162*)g_wq_l; }
    else if (SEL == 3) { hi = (__nv_bfloat162*)g_wkv_h;lo = (__nv_bfloat162*)g_wkv_l;}
    else               { hi = (__nv_bfloat162*)g_wp_h; lo = (__nv_bfloat162*)g_wp_l; }

    int stride = gridDim.x * blockDim.x;
    for (int i = blockIdx.x*blockDim.x + threadIdx.x; i < n4; i += stride) {
        float4 v = in[i];
        __nv_bfloat162 h0, l0, h1, l1;
        split2(v.x, v.y, h0, l0);
        split2(v.z, v.w, h1, l1);
        hi[2*i]   = h0; hi[2*i+1] = h1;
        lo[2*i]   = l0; lo[2*i+1] = l1;
    }
}

// ---------------------------------------------------------------------------
// Mask prep: detect storage width of the bool padding_mask (u8 / i32 / f32)
// ---------------------------------------------------------------------------
__global__ void mask_prep(const unsigned char* __restrict__ raw)
{
    __shared__ int nzA, nzB;
    if (threadIdx.x == 0) { nzA = 0; nzB = 0; }
    __syncthreads();
    int la = 0, lb = 0;
    for (int i = threadIdx.x; i < BB*MM; i += blockDim.x) {
        unsigned char v = raw[i];
        int r = i & 3;
        if (v && r == 1) la++;
        if (v && r >= 2) lb++;
    }
    if (la) atomicAdd(&nzA, la);
    if (lb) atomicAdd(&nzB, lb);
    __syncthreads();
    int mode = (nzA > 0) ? 0 : ((nzB > 0) ? 1 : 2);
    for (int i = threadIdx.x; i < BB*MM; i += blockDim.x) {
        bool masked;
        if (mode == 0)      masked = raw[i] != 0;
        else if (mode == 1) masked = ((const float*)raw)[i] != 0.0f;
        else                masked = ((const int*)raw)[i] != 0;
        g_maskbias[i] = masked ? -1e30f : 0.0f;
    }
}

// ---------------------------------------------------------------------------
// HMMA GEMM (R8 structure, pre-split operands chosen device-side by EPI):
// C[Mr,Nc] = A[Mr,K] @ B[Nc,K]^T via bf16x3. 128x128 CTA tile, BK=32,
// 8 warps (4x2), per-warp 32x64, fp32 accum. Loader is pure uint4 copies.
// EPI 0: A=q,B=Wq,K=CC -> Q scatter (split)
// EPI 1: A=kv,B=Wkv,K=KVD -> K/V scatter (split)
// EPI 2: A=g_x,B=Wproj,K=CC -> bias + dense fp32 out
// ---------------------------------------------------------------------------
#define SAK 40   // smem tile stride in bf16 elements (80 B: conflict-free frags)

template<int EPI>
__global__ __launch_bounds__(256)
void hmma_gemm(const float* __restrict__ bias, float* __restrict__ Cout)
{
    __shared__ __align__(16) unsigned short sAh[128*SAK];
    __shared__ __align__(16) unsigned short sAl[128*SAK];
    __shared__ __align__(16) unsigned short sBh[128*SAK];
    __shared__ __align__(16) unsigned short sBl[128*SAK];

    // device-side operand binding (the R9/R10 host-decay bug fix)
    const __nv_bfloat16 *Ah, *Al, *Bh, *Bl;
    if (EPI == 0)      { Ah = g_q_h;  Al = g_q_l;  Bh = g_wq_h;  Bl = g_wq_l;  }
    else if (EPI == 1) { Ah = g_kv_h; Al = g_kv_l; Bh = g_wkv_h; Bl = g_wkv_l; }
    else               { Ah = g_xh;   Al = g_xl;   Bh = g_wp_h;  Bl = g_wp_l;  }
    const int K  = (EPI == 1) ? KVD : CC;

    const int tid  = threadIdx.x;
    const int wid  = tid >> 5;
    const int lane = tid & 31;
    const int g    = lane >> 2;
    const int t4   = lane & 3;
    const int m0w  = (wid & 3) * 32;
    const int n0w  = (wid >> 2) * 64;
    const int row0 = blockIdx.y * 128;
    const int col0 = blockIdx.x * 128;

    // loader mapping: 2 threads per row, 16 bf16 elements each
    const int lrow = tid >> 1;
    const int lseg = (tid & 1) * 16;
    const __nv_bfloat16* Ahp = Ah + (size_t)(row0 + lrow) * K + lseg;
    const __nv_bfloat16* Alp = Al + (size_t)(row0 + lrow) * K + lseg;
    const __nv_bfloat16* Bhp = Bh + (size_t)(col0 + lrow) * K + lseg;
    const __nv_bfloat16* Blp = Bl + (size_t)(col0 + lrow) * K + lseg;
    const int soff = lrow*SAK + lseg;

    float acc[2][8][4];
    #pragma unroll
    for (int mt = 0; mt < 2; mt++)
        #pragma unroll
        for (int nt = 0; nt < 8; nt++)
            #pragma unroll
            for (int i = 0; i < 4; i++) acc[mt][nt][i] = 0.0f;

    // prologue: stage chunk 0
    {
        *(uint4*)(sAh + soff)     = *(const uint4*)(Ahp);
        *(uint4*)(sAh + soff + 8) = *(const uint4*)(Ahp + 8);
        *(uint4*)(sAl + soff)     = *(const uint4*)(Alp);
        *(uint4*)(sAl + soff + 8) = *(const uint4*)(Alp + 8);
        *(uint4*)(sBh + soff)     = *(const uint4*)(Bhp);
        *(uint4*)(sBh + soff + 8) = *(const uint4*)(Bhp + 8);
        *(uint4*)(sBl + soff)     = *(const uint4*)(Blp);
        *(uint4*)(sBl + soff + 8) = *(const uint4*)(Blp + 8);
    }
    __syncthreads();

    const int nk = K >> 5;
    for (int t = 0; t < nk; t++) {
        const bool more = (t + 1 < nk);
        uint4 pah0, pah1, pal0, pal1, pbh0, pbh1, pbl0, pbl1;
        if (more) {
            const int o = (t+1)*32;
            pah0 = *(const uint4*)(Ahp + o);  pah1 = *(const uint4*)(Ahp + o + 8);
            pal0 = *(const uint4*)(Alp + o);  pal1 = *(const uint4*)(Alp + o + 8);
            pbh0 = *(const uint4*)(Bhp + o);  pbh1 = *(const uint4*)(Bhp + o + 8);
            pbl0 = *(const uint4*)(Blp + o);  pbl1 = *(const uint4*)(Blp + o + 8);
        }

        #pragma unroll
        for (int ks = 0; ks < 2; ks++) {
            unsigned ah[2][4], al[2][4];
            #pragma unroll
            for (int mt = 0; mt < 2; mt++) {
                const int base = (m0w + mt*16 + g)*SAK + ks*16 + 2*t4;
                ah[mt][0] = *(const unsigned*)(sAh + base);
                ah[mt][1] = *(const unsigned*)(sAh + base + 8*SAK);
                ah[mt][2] = *(const unsigned*)(sAh + base + 8);
                ah[mt][3] = *(const unsigned*)(sAh + base + 8*SAK + 8);
                al[mt][0] = *(const unsigned*)(sAl + base);
                al[mt][1] = *(const unsigned*)(sAl + base + 8*SAK);
                al[mt][2] = *(const unsigned*)(sAl + base + 8);
                al[mt][3] = *(const unsigned*)(sAl + base + 8*SAK + 8);
            }
            #pragma unroll
            for (int nt = 0; nt < 8; nt++) {
                const int bb = (n0w + nt*8 + g)*SAK + ks*16 + 2*t4;
                unsigned bh[2] = { *(const unsigned*)(sBh + bb),
                                   *(const unsigned*)(sBh + bb + 8) };
                unsigned bl[2] = { *(const unsigned*)(sBl + bb),
                                   *(const unsigned*)(sBl + bb + 8) };
                #pragma unroll
                for (int mt = 0; mt < 2; mt++) {
                    mma16816(acc[mt][nt], ah[mt], bh);
                    mma16816(acc[mt][nt], ah[mt], bl);
                    mma16816(acc[mt][nt], al[mt], bh);
                }
            }
        }
        __syncthreads();
        if (more) {
            *(uint4*)(sAh + soff)     = pah0;
            *(uint4*)(sAh + soff + 8) = pah1;
            *(uint4*)(sAl + soff)     = pal0;
            *(uint4*)(sAl + soff + 8) = pal1;
            *(uint4*)(sBh + soff)     = pbh0;
            *(uint4*)(sBh + soff + 8) = pbh1;
            *(uint4*)(sBl + soff)     = pbl0;
            *(uint4*)(sBl + soff + 8) = pbl1;
        }
        __syncthreads();
    }

    // Epilogue
    #pragma unroll
    for (int mt = 0; mt < 2; mt++)
    #pragma unroll
    for (int nt = 0; nt < 8; nt++) {
        const int c = col0 + n0w + nt*8 + 2*t4;
        #pragma unroll
        for (int half = 0; half < 2; half++) {
            const int r = row0 + m0w + mt*16 + g + half*8;
            float2 v = make_float2(acc[mt][nt][half*2], acc[mt][nt][half*2+1]);
            if (EPI == 0) {
                v.x *= QK_SCALE; v.y *= QK_SCALE;
                int b = r >> 10, n = r & 1023, h = c >> 6, dd = c & 63;
                __nv_bfloat162 hh, ll;
                split2(v.x, v.y, hh, ll);
                size_t i = (((size_t)(b*HH + h))*NN + n)*DD + dd;
                *(__nv_bfloat162*)&g_qhh[i] = hh;
                *(__nv_bfloat162*)&g_qhl[i] = ll;
            } else if (EPI == 1) {
                int b = r >> 11, m = r & 2047;
                int two = c >> 10, h = (c >> 6) & 15, dd = c & 63;
                __nv_bfloat162 hh, ll;
                split2(v.x, v.y, hh, ll);
                if (two) {  // V: transposed [b,h,d,m]
                    size_t base = (((size_t)(b*HH + h))*DD + dd)*MM + m;
                    g_vh[base]      = __low2bfloat16(hh);
                    g_vh[base + MM] = __high2bfloat16(hh);
                    g_vl[base]      = __low2bfloat16(ll);
                    g_vl[base + MM] = __high2bfloat16(ll);
                } else {    // K: natural [b,h,m,d]
                    size_t i = (((size_t)(b*HH + h))*MM + m)*DD + dd;
                    *(__nv_bfloat162*)&g_kh[i] = hh;
                    *(__nv_bfloat162*)&g_kl[i] = ll;
                }
            } else {
                v.x += bias[c]; v.y += bias[c+1];
                *(float2*)&Cout[(size_t)r * CC + c] = v;
            }
        }
    }
}

// ---------------------------------------------------------------------------
// HMMA attention (R8 core, validated): QT=128 x MT=64, 8 warps, bf16x3 QK+PV,
// P register pass-through, deferred normalization. Epilogue writes split
// g_xh/g_xl for the output projection. Globals referenced device-side only.
// ---------------------------------------------------------------------------
#define SDB 144                 // smem row stride bytes (72 bf16)
#define AS_QH 0
#define AS_QL 18432
#define AS_KH 36864
#define AS_KL 55296
#define AS_VH 73728
#define AS_VL 92160
#define KVBUF 9216              // one K or V buffer: 64*144
#define ATT_SMEM_BYTES 110592

__device__ __forceinline__ void attn_load_kv(char* smc,
        const __nv_bfloat16* kh, const __nv_bfloat16* kl,
        const __nv_bfloat16* vh, const __nv_bfloat16* vl,
        int m0, int buf, int tid)
{
    const int bo = buf * KVBUF;
    #pragma unroll
    for (int j = 0; j < 2; j++) {
        int idx = tid + j*256;          // 0..511
        int r = idx >> 3;               // row 0..63
        int o = (idx & 7) * 16;         // byte offset within 128B row
        cpasync16(smc + AS_KH + bo + r*SDB + o, (const char*)kh + ((size_t)(m0 + r))*128 + o);
        cpasync16(smc + AS_KL + bo + r*SDB + o, (const char*)kl + ((size_t)(m0 + r))*128 + o);
        cpasync16(smc + AS_VH + bo + r*SDB + o, (const char*)vh + ((size_t)r*MM + m0)*2 + o);
        cpasync16(smc + AS_VL + bo + r*SDB + o, (const char*)vl + ((size_t)r*MM + m0)*2 + o);
    }
}

__global__ __launch_bounds__(256)
void attn_hmma(const float* __restrict__ alibi)
{
    extern __shared__ char smc[];
    const int tid  = threadIdx.x;
    const int w    = tid >> 5;
    const int lane = tid & 31;
    const int g    = lane >> 2;
    const int t4   = lane & 3;
    const int bh   = blockIdx.y;
    const int n0   = blockIdx.x * 128;
    const int b    = bh >> 4, h = bh & 15;

    const __nv_bfloat16* qh = g_qhh + ((size_t)bh*NN + n0)*DD;
    const __nv_bfloat16* ql = g_qhl + ((size_t)bh*NN + n0)*DD;
    const __nv_bfloat16* kh = g_kh + (size_t)bh*MM*DD;
    const __nv_bfloat16* kl = g_kl + (size_t)bh*MM*DD;
    const __nv_bfloat16* vh = g_vh + (size_t)bh*DD*MM;
    const __nv_bfloat16* vl = g_vl + (size_t)bh*DD*MM;
    const float* ab   = alibi + ((size_t)(bh*NN) + n0)*MM;
    const float* mrow = g_maskbias + (size_t)b*MM;

    #pragma unroll
    for (int j = 0; j < 4; j++) {
        int idx = tid + j*256;
        int r = idx >> 3, o = (idx & 7) * 16;
        cpasync16(smc + AS_QH + r*SDB + o, (const char*)qh + (size_t)r*128 + o);
        cpasync16(smc + AS_QL + r*SDB + o, (const char*)ql + (size_t)r*128 + o);
    }
    attn_load_kv(smc, kh, kl, vh, vl, 0, 0, tid);
    CP_COMMIT();

    float oacc[8][4];
    #pragma unroll
    for (int nt = 0; nt < 8; nt++)
        #pragma unroll
        for (int i = 0; i < 4; i++) oacc[nt][i] = 0.0f;
    float lp0 = 0.0f, lp1 = 0.0f;

    const int qrow = w*16 + g;

    #pragma unroll 1
    for (int t = 0; t < MM/64; t++) {
        const int m0 = t * 64;
        const int buf = t & 1;

        CP_WAIT0();
        __syncthreads();
        if (t + 1 < MM/64) {
            attn_load_kv(smc, kh, kl, vh, vl, m0 + 64, buf ^ 1, tid);
            CP_COMMIT();
        }

        float2 a0r[8], a1r[8], mb[8];
        #pragma unroll
        for (int nt = 0; nt < 8; nt++) {
            const int mc = m0 + nt*8 + 2*t4;
            a0r[nt] = *(const float2*)&ab[(size_t)qrow*MM + mc];
            a1r[nt] = *(const float2*)&ab[(size_t)(qrow+8)*MM + mc];
            mb[nt]  = *(const float2*)&mrow[mc];
        }

        float sacc[8][4];
        #pragma unroll
        for (int nt = 0; nt < 8; nt++)
            #pragma unroll
            for (int i = 0; i < 4; i++) sacc[nt][i] = 0.0f;

        const char* kbh = smc + AS_KH + buf*KVBUF;
        const char* kbl = smc + AS_KL + buf*KVBUF;
        #pragma unroll
        for (int kt = 0; kt < 4; kt++) {
            const int abase = qrow*SDB + kt*32 + t4*4;
            unsigned ah[4], al[4];
            ah[0] = *(const unsigned*)(smc + AS_QH + abase);
            ah[1] = *(const unsigned*)(smc + AS_QH + abase + 8*SDB);
            ah[2] = *(const unsigned*)(smc + AS_QH + abase + 16);
            ah[3] = *(const unsigned*)(smc + AS_QH + abase + 8*SDB + 16);
            al[0] = *(const unsigned*)(smc + AS_QL + abase);
            al[1] = *(const unsigned*)(smc + AS_QL + abase + 8*SDB);
            al[2] = *(const unsigned*)(smc + AS_QL + abase + 16);
            al[3] = *(const unsigned*)(smc + AS_QL + abase + 8*SDB + 16);
            #pragma unroll
            for (int nt = 0; nt < 8; nt++) {
                const int bb = (nt*8 + g)*SDB + kt*32 + t4*4;
                unsigned bhf[2] = { *(const unsigned*)(kbh + bb),
                                    *(const unsigned*)(kbh + bb + 16) };
                unsigned blf[2] = { *(const unsigned*)(kbl + bb),
                                    *(const unsigned*)(kbl + bb + 16) };
                mma16816(sacc[nt], ah, bhf);
                mma16816(sacc[nt], ah, blf);
                mma16816(sacc[nt], al, bhf);
            }
        }

        unsigned ph0[8], ph1[8], pl0[8], pl1[8];
        #pragma unroll
        for (int nt = 0; nt < 8; nt++) {
            float p00 = __expf(fminf(sacc[nt][0] + a0r[nt].x + mb[nt].x, 60.0f));
            float p01 = __expf(fminf(sacc[nt][1] + a0r[nt].y + mb[nt].y, 60.0f));
            float p10 = __expf(fminf(sacc[nt][2] + a1r[nt].x + mb[nt].x, 60.0f));
            float p11 = __expf(fminf(sacc[nt][3] + a1r[nt].y + mb[nt].y, 60.0f));
            lp0 += p00 + p01;
            lp1 += p10 + p11;
            __nv_bfloat162 hh, ll;
            split2(p00, p01, hh, ll);
            ph0[nt] = *reinterpret_cast<unsigned*>(&hh);
            pl0[nt] = *reinterpret_cast<unsigned*>(&ll);
            split2(p10, p11, hh, ll);
            ph1[nt] = *reinterpret_cast<unsigned*>(&hh);
            pl1[nt] = *reinterpret_cast<unsigned*>(&ll);
        }

        const char* vbh = smc + AS_VH + buf*KVBUF;
        const char* vbl = smc + AS_VL + buf*KVBUF;
        #pragma unroll
        for (int kt = 0; kt < 4; kt++) {
            unsigned aH[4] = { ph0[2*kt], ph1[2*kt], ph0[2*kt+1], ph1[2*kt+1] };
            unsigned aL[4] = { pl0[2*kt], pl1[2*kt], pl0[2*kt+1], pl1[2*kt+1] };
            #pragma unroll
            for (int nt = 0; nt < 8; nt++) {
                const int bb = (nt*8 + g)*SDB + kt*32 + t4*4;
                unsigned bhf[2] = { *(const unsigned*)(vbh + bb),
                                    *(const unsigned*)(vbh + bb + 16) };
                unsigned blf[2] = { *(const unsigned*)(vbl + bb),
                                    *(const unsigned*)(vbl + bb + 16) };
                mma16816(oacc[nt], aH, bhf);
                mma16816(oacc[nt], aH, blf);
                mma16816(oacc[nt], aL, bhf);
            }
        }
    }

    lp0 += __shfl_xor_sync(0xFFFFFFFF, lp0, 1);
    lp0 += __shfl_xor_sync(0xFFFFFFFF, lp0, 2);
    lp1 += __shfl_xor_sync(0xFFFFFFFF, lp1, 1);
    lp1 += __shfl_xor_sync(0xFFFFFFFF, lp1, 2);
    const float li0 = 1.0f / lp0;
    const float li1 = 1.0f / lp1;

    // write normalized output split to g_xh/g_xl [b, n, h*64 + d]
    const size_t xo = ((size_t)b*NN + n0 + w*16)*CC + h*DD;
    #pragma unroll
    for (int nt = 0; nt < 8; nt++) {
        const int dc = nt*8 + 2*t4;
        __nv_bfloat162 hh, ll;
        split2(oacc[nt][0]*li0, oacc[nt][1]*li0, hh, ll);
        *(__nv_bfloat162*)&g_xh[xo + (size_t)g*CC + dc] = hh;
        *(__nv_bfloat162*)&g_xl[xo + (size_t)g*CC + dc] = ll;
        split2(oacc[nt][2]*li1, oacc[nt][3]*li1, hh, ll);
        *(__nv_bfloat162*)&g_xh[xo + (size_t)(g+8)*CC + dc] = hh;
        *(__nv_bfloat162*)&g_xl[xo + (size_t)(g+8)*CC + dc] = ll;
    }
}

// ---------------------------------------------------------------------------
extern "C" void kernel_launch(void* const* d_in, const int* in_sizes, int n_in,
                              void* d_out, int out_size)
{
    const float *q = nullptr, *kv = nullptr, *alibi = nullptr;
    const float *Wq = nullptr, *Wkv = nullptr, *Wproj = nullptr, *bproj = nullptr;
    const void  *maskp = nullptr;
    int wseen = 0;
    for (int i = 0; i < n_in; i++) {
        switch (in_sizes[i]) {
            case 2097152:  q     = (const float*)d_in[i]; break;           // (2,1024,1024)
            case 3145728:  kv    = (const float*)d_in[i]; break;           // (2,2048,768)
            case 67108864: alibi = (const float*)d_in[i]; break;           // (2,16,1024,2048)
            case 4096:     maskp = d_in[i]; break;                          // (2,2048) bool
            case 1572864:  Wkv   = (const float*)d_in[i]; break;           // (2048,768)
            case 1024:     bproj = (const float*)d_in[i]; break;           // (1024,)
            case 1048576:                                                   // Wq then Wproj
                if (wseen++ == 0) Wq = (const float*)d_in[i];
                else              Wproj = (const float*)d_in[i];
                break;
            default: break;
        }
    }
    float* out = (float*)d_out;
    (void)out_size;

    cudaFuncSetAttribute(attn_hmma,
                         cudaFuncAttributeMaxDynamicSharedMemorySize, ATT_SMEM_BYTES);

    mask_prep<<<1, 256>>>((const unsigned char*)maskp);

    // Pre-split all GEMM operands to bf16 hi/lo (destinations bound device-side)
    split_arr<0><<<512, 256>>>((const float4*)q,     BB*NN*CC/4);
    split_arr<1><<<512, 256>>>((const float4*)kv,    BB*MM*KVD/4);
    split_arr<2><<<512, 256>>>((const float4*)Wq,    CC*CC/4);
    split_arr<3><<<512, 256>>>((const float4*)Wkv,   2*CC*KVD/4);
    split_arr<4><<<512, 256>>>((const float4*)Wproj, CC*CC/4);

    // Q projection -> split bf16 hi/lo [b,h,n,d] (scaled)
    hmma_gemm<0><<<dim3(CC/128, (BB*NN)/128), 256>>>(nullptr, nullptr);
    // KV projection -> K hi/lo [b,h,m,d]; V hi/lo transposed [b,h,d,m]
    hmma_gemm<1><<<dim3((2*CC)/128, (BB*MM)/128), 256>>>(nullptr, nullptr);
    // Fused HMMA attention (outputs pre-split g_xh/g_xl)
    attn_hmma<<<dim3(NN/128, BB*HH), 256, ATT_SMEM_BYTES>>>(alibi);
    // Output projection
    hmma_gemm<2><<<dim3(CC/128, (BB*NN)/128), 256>>>(bproj, out);
}

// round 12
// speedup vs baseline: 1.0940x; 1.0940x over previous
#include <cuda_runtime.h>
#include <cuda_bf16.h>
#include <cstdint>

// Problem constants
#define HH   16
#define DD   64
#define BB   2
#define NN   1024
#define MM   2048
#define CC   1024
#define KVD  768
#define QK_SCALE 0.125f   // 64^-0.5

// ---------------------------------------------------------------------------
// Scratch (allocation-free: __device__ globals).
// ONLY referenced from device code (host-decay of __device__ symbols was the
// R9/R10 bug).
// ---------------------------------------------------------------------------
__device__ __align__(16) __nv_bfloat16 g_qhh[BB*HH*NN*DD];  // scaled Q hi [b,h,n,d]
__device__ __align__(16) __nv_bfloat16 g_qhl[BB*HH*NN*DD];  // scaled Q lo
__device__ __align__(16) __nv_bfloat16 g_kh [BB*HH*MM*DD];  // K hi [b,h,m,d]
__device__ __align__(16) __nv_bfloat16 g_kl [BB*HH*MM*DD];  // K lo
__device__ __align__(16) __nv_bfloat16 g_vh [BB*HH*DD*MM];  // V hi TRANSPOSED [b,h,d,m]
__device__ __align__(16) __nv_bfloat16 g_vl [BB*HH*DD*MM];  // V lo TRANSPOSED
__device__ __align__(16) __nv_bfloat16 g_q_h [BB*NN*CC];    // pre-split GEMM operands
__device__ __align__(16) __nv_bfloat16 g_q_l [BB*NN*CC];
__device__ __align__(16) __nv_bfloat16 g_kv_h[BB*MM*KVD];
__device__ __align__(16) __nv_bfloat16 g_kv_l[BB*MM*KVD];
__device__ __align__(16) __nv_bfloat16 g_wq_h[CC*CC];
__device__ __align__(16) __nv_bfloat16 g_wq_l[CC*CC];
__device__ __align__(16) __nv_bfloat16 g_wkv_h[2*CC*KVD];
__device__ __align__(16) __nv_bfloat16 g_wkv_l[2*CC*KVD];
__device__ __align__(16) __nv_bfloat16 g_wp_h[CC*CC];
__device__ __align__(16) __nv_bfloat16 g_wp_l[CC*CC];
__device__ __align__(16) __nv_bfloat16 g_xh[BB*NN*CC];      // attn out hi [b,n,h*D+d]
__device__ __align__(16) __nv_bfloat16 g_xl[BB*NN*CC];      // attn out lo
__device__ __align__(16) float g_maskbias[BB*MM];           // 0 or -1e30

// ---------------------------------------------------------------------------
// Helpers
// ---------------------------------------------------------------------------
__device__ __forceinline__ void cpasync16(void* smem, const void* gmem) {
    unsigned s = (unsigned)__cvta_generic_to_shared(smem);
    asm volatile("cp.async.ca.shared.global [%0], [%1], 16;" :: "r"(s), "l"(gmem));
}
#define CP_COMMIT() asm volatile("cp.async.commit_group;" ::: "memory")
#define CP_WAIT0()  asm volatile("cp.async.wait_group 0;" ::: "memory")
#define CP_WAIT1()  asm volatile("cp.async.wait_group 1;" ::: "memory")

// Warp-level HMMA: D(16x8,f32) += A(16x16,bf16 row) * B(16x8,bf16 col)
__device__ __forceinline__ void mma16816(float* d, const unsigned* a, const unsigned* b)
{
    asm volatile(
        "mma.sync.aligned.m16n8k16.row.col.f32.bf16.bf16.f32 "
        "{%0,%1,%2,%3}, {%4,%5,%6,%7}, {%8,%9}, {%0,%1,%2,%3};"
        : "+f"(d[0]), "+f"(d[1]), "+f"(d[2]), "+f"(d[3])
        : "r"(a[0]), "r"(a[1]), "r"(a[2]), "r"(a[3]), "r"(b[0]), "r"(b[1]));
}

// fp32x2 -> bf16x2 hi/lo
__device__ __forceinline__ void split2(float x, float y,
                                       __nv_bfloat162& h, __nv_bfloat162& l)
{
    h = __floats2bfloat162_rn(x, y);
    float rx = x - __low2float(h);
    float ry = y - __high2float(h);
    l = __floats2bfloat162_rn(rx, ry);
}

// ---------------------------------------------------------------------------
// Prep: one fused kernel splits all 5 fp32 operand arrays to bf16 hi/lo.
// Destination globals are bound in device code.
// ---------------------------------------------------------------------------
#define N4_Q   (BB*NN*CC/4)
#define N4_KV  (BB*MM*KVD/4)
#define N4_WQ  (CC*CC/4)
#define N4_WKV (2*CC*KVD/4)
#define N4_WP  (CC*CC/4)
#define N4_TOT (N4_Q + N4_KV + N4_WQ + N4_WKV + N4_WP)

__global__ void split_all(const float4* __restrict__ q, const float4* __restrict__ kv,
                          const float4* __restrict__ wq, const float4* __restrict__ wkv,
                          const float4* __restrict__ wp)
{
    int stride = gridDim.x * blockDim.x;
    for (int i = blockIdx.x*blockDim.x + threadIdx.x; i < N4_TOT; i += stride) {
        const float4* in;
        __nv_bfloat162 *hi, *lo;
        int j = i;
        if (j < N4_Q) {
            in = q;  hi = (__nv_bfloat162*)g_q_h;  lo = (__nv_bfloat162*)g_q_l;
        } else if ((j -= N4_Q) < N4_KV) {
            in = kv; hi = (__nv_bfloat162*)g_kv_h; lo = (__nv_bfloat162*)g_kv_l;
        } else if ((j -= N4_KV) < N4_WQ) {
            in = wq; hi = (__nv_bfloat162*)g_wq_h; lo = (__nv_bfloat162*)g_wq_l;
        } else if ((j -= N4_WQ) < N4_WKV) {
            in = wkv; hi = (__nv_bfloat162*)g_wkv_h; lo = (__nv_bfloat162*)g_wkv_l;
        } else {
            j -= N4_WKV;
            in = wp; hi = (__nv_bfloat162*)g_wp_h; lo = (__nv_bfloat162*)g_wp_l;
        }
        float4 v = in[j];
        __nv_bfloat162 h0, l0, h1, l1;
        split2(v.x, v.y, h0, l0);
        split2(v.z, v.w, h1, l1);
        hi[2*j]   = h0; hi[2*j+1] = h1;
        lo[2*j]   = l0; lo[2*j+1] = l1;
    }
}

// ---------------------------------------------------------------------------
// Mask prep: detect storage width of the bool padding_mask (u8 / i32 / f32)
// ---------------------------------------------------------------------------
__global__ void mask_prep(const unsigned char* __restrict__ raw)
{
    __shared__ int nzA, nzB;
    if (threadIdx.x == 0) { nzA = 0; nzB = 0; }
    __syncthreads();
    int la = 0, lb = 0;
    for (int i = threadIdx.x; i < BB*MM; i += blockDim.x) {
        unsigned char v = raw[i];
        int r = i & 3;
        if (v && r == 1) la++;
        if (v && r >= 2) lb++;
    }
    if (la) atomicAdd(&nzA, la);
    if (lb) atomicAdd(&nzB, lb);
    __syncthreads();
    int mode = (nzA > 0) ? 0 : ((nzB > 0) ? 1 : 2);
    for (int i = threadIdx.x; i < BB*MM; i += blockDim.x) {
        bool masked;
        if (mode == 0)      masked = raw[i] != 0;
        else if (mode == 1) masked = ((const float*)raw)[i] != 0.0f;
        else                masked = ((const int*)raw)[i] != 0;
        g_maskbias[i] = masked ? -1e30f : 0.0f;
    }
}

// ---------------------------------------------------------------------------
// GEMM body: C[.,.] = A[.,K] @ B[.,K]^T via bf16x3 HMMA.
// 128x128 CTA tile, BK=16, cp.async double-buffered (48 KB smem), 8 warps
// (4x2), per-warp 32x64, fp32 accum. 2 CTAs/SM.
// Smem row = 16 bf16 (32 B) padded to SAK=24 shorts (48 B): fragment banks
// (12g + t4) mod 32 all-distinct; 16B-aligned for cp.async.
// ---------------------------------------------------------------------------
#define SAK   24
#define GARRS (128*SAK)       // one array in shorts (3072)

__device__ __forceinline__ void gemm_body(
        unsigned short (*smb)[4][GARRS],   // [2][4][GARRS]: Ah,Al,Bh,Bl
        const __nv_bfloat16* __restrict__ Ah, const __nv_bfloat16* __restrict__ Al,
        const __nv_bfloat16* __restrict__ Bh, const __nv_bfloat16* __restrict__ Bl,
        int K, int row0, int col0, int epi,
        const float* __restrict__ bias, float* __restrict__ Cout)
{
    const int tid  = threadIdx.x;
    const int wid  = tid >> 5;
    const int lane = tid & 31;
    const int g    = lane >> 2;
    const int t4   = lane & 3;
    const int m0w  = (wid & 3) * 32;
    const int n0w  = (wid >> 2) * 64;

    // loader mapping: 2 threads per row, 8 bf16 (16 B) each
    const int lrow  = tid >> 1;
    const int lhalf = (tid & 1) * 8;            // element offset
    const int so    = lrow*SAK + lhalf;          // smem short offset
    const __nv_bfloat16* Ahp = Ah + (size_t)(row0 + lrow) * K + lhalf;
    const __nv_bfloat16* Alp = Al + (size_t)(row0 + lrow) * K + lhalf;
    const __nv_bfloat16* Bhp = Bh + (size_t)(col0 + lrow) * K + lhalf;
    const __nv_bfloat16* Blp = Bl + (size_t)(col0 + lrow) * K + lhalf;

    float acc[2][8][4];
    #pragma unroll
    for (int mt = 0; mt < 2; mt++)
        #pragma unroll
        for (int nt = 0; nt < 8; nt++)
            #pragma unroll
            for (int i = 0; i < 4; i++) acc[mt][nt][i] = 0.0f;

    // prologue: stage chunk 0 into buffer 0
    {
        cpasync16(&smb[0][0][so], Ahp);
        cpasync16(&smb[0][1][so], Alp);
        cpasync16(&smb[0][2][so], Bhp);
        cpasync16(&smb[0][3][so], Blp);
        CP_COMMIT();
    }

    const int nk = K >> 4;
    for (int t = 0; t < nk; t++) {
        const int buf = t & 1;
        if (t + 1 < nk) {
            const int o = (t+1)*16;
            const int nb = buf ^ 1;
            cpasync16(&smb[nb][0][so], Ahp + o);
            cpasync16(&smb[nb][1][so], Alp + o);
            cpasync16(&smb[nb][2][so], Bhp + o);
            cpasync16(&smb[nb][3][so], Blp + o);
            CP_COMMIT();
            CP_WAIT1();          // chunk t complete (t+1 may remain in flight)
        } else {
            CP_WAIT0();
        }
        __syncthreads();

        const unsigned short* sAh = smb[buf][0];
        const unsigned short* sAl = smb[buf][1];
        const unsigned short* sBh = smb[buf][2];
        const unsigned short* sBl = smb[buf][3];

        unsigned ah[2][4], al[2][4];
        #pragma unroll
        for (int mt = 0; mt < 2; mt++) {
            const int base = (m0w + mt*16 + g)*SAK + 2*t4;
            ah[mt][0] = *(const unsigned*)(sAh + base);
            ah[mt][1] = *(const unsigned*)(sAh + base + 8*SAK);
            ah[mt][2] = *(const unsigned*)(sAh + base + 8);
            ah[mt][3] = *(const unsigned*)(sAh + base + 8*SAK + 8);
            al[mt][0] = *(const unsigned*)(sAl + base);
            al[mt][1] = *(const unsigned*)(sAl + base + 8*SAK);
            al[mt][2] = *(const unsigned*)(sAl + base + 8);
            al[mt][3] = *(const unsigned*)(sAl + base + 8*SAK + 8);
        }
        #pragma unroll
        for (int nt = 0; nt < 8; nt++) {
            const int bb = (n0w + nt*8 + g)*SAK + 2*t4;
            unsigned bh[2] = { *(const unsigned*)(sBh + bb),
                               *(const unsigned*)(sBh + bb + 8) };
            unsigned bl[2] = { *(const unsigned*)(sBl + bb),
                               *(const unsigned*)(sBl + bb + 8) };
            #pragma unroll
            for (int mt = 0; mt < 2; mt++) {
                mma16816(acc[mt][nt], ah[mt], bh);
                mma16816(acc[mt][nt], ah[mt], bl);
                mma16816(acc[mt][nt], al[mt], bh);
            }
        }
        __syncthreads();
    }

    // Epilogue
    #pragma unroll
    for (int mt = 0; mt < 2; mt++)
    #pragma unroll
    for (int nt = 0; nt < 8; nt++) {
        const int c = col0 + n0w + nt*8 + 2*t4;
        #pragma unroll
        for (int half = 0; half < 2; half++) {
            const int r = row0 + m0w + mt*16 + g + half*8;
            float2 v = make_float2(acc[mt][nt][half*2], acc[mt][nt][half*2+1]);
            if (epi == 0) {
                v.x *= QK_SCALE; v.y *= QK_SCALE;
                int b = r >> 10, n = r & 1023, h = c >> 6, dd = c & 63;
                __nv_bfloat162 hh, ll;
                split2(v.x, v.y, hh, ll);
                size_t i = (((size_t)(b*HH + h))*NN + n)*DD + dd;
                *(__nv_bfloat162*)&g_qhh[i] = hh;
                *(__nv_bfloat162*)&g_qhl[i] = ll;
            } else if (epi == 1) {
                int b = r >> 11, m = r & 2047;
                int two = c >> 10, h = (c >> 6) & 15, dd = c & 63;
                __nv_bfloat162 hh, ll;
                split2(v.x, v.y, hh, ll);
                if (two) {  // V: transposed [b,h,d,m]
                    size_t base = (((size_t)(b*HH + h))*DD + dd)*MM + m;
                    g_vh[base]      = __low2bfloat16(hh);
                    g_vh[base + MM] = __high2bfloat16(hh);
                    g_vl[base]      = __low2bfloat16(ll);
                    g_vl[base + MM] = __high2bfloat16(ll);
                } else {    // K: natural [b,h,m,d]
                    size_t i = (((size_t)(b*HH + h))*MM + m)*DD + dd;
                    *(__nv_bfloat162*)&g_kh[i] = hh;
                    *(__nv_bfloat162*)&g_kl[i] = ll;
                }
            } else {
                v.x += bias[c]; v.y += bias[c+1];
                *(float2*)&Cout[(size_t)r * CC + c] = v;
            }
        }
    }
}

// Fused Q-projection (128 CTAs) + KV-projection (512 CTAs)
__global__ __launch_bounds__(256, 2)
void qkv_gemm()
{
    __shared__ __align__(16) unsigned short smb[2][4][GARRS];   // 48 KB
    const int bx = blockIdx.x;
    if (bx < 128) {
        gemm_body(smb, g_q_h, g_q_l, g_wq_h, g_wq_l,
                  CC, (bx >> 3)*128, (bx & 7)*128, 0, nullptr, nullptr);
    } else {
        const int b2 = bx - 128;
        gemm_body(smb, g_kv_h, g_kv_l, g_wkv_h, g_wkv_l,
                  KVD, (b2 >> 4)*128, (b2 & 15)*128, 1, nullptr, nullptr);
    }
}

// Output projection (128 CTAs)
__global__ __launch_bounds__(256, 2)
void oproj_gemm(const float* __restrict__ bias, float* __restrict__ out)
{
    __shared__ __align__(16) unsigned short smb[2][4][GARRS];
    const int bx = blockIdx.x;
    gemm_body(smb, g_xh, g_xl, g_wp_h, g_wp_l,
              CC, (bx >> 3)*128, (bx & 7)*128, 2, bias, out);
}

// ---------------------------------------------------------------------------
// HMMA attention (R8/R11 core, validated — FROZEN): QT=128 x MT=64, 8 warps,
// bf16x3 QK+PV, P register pass-through, deferred normalization.
// ---------------------------------------------------------------------------
#define SDB 144                 // smem row stride bytes (72 bf16)
#define AS_QH 0
#define AS_QL 18432
#define AS_KH 36864
#define AS_KL 55296
#define AS_VH 73728
#define AS_VL 92160
#define KVBUF 9216              // one K or V buffer: 64*144
#define ATT_SMEM_BYTES 110592

__device__ __forceinline__ void attn_load_kv(char* smc,
        const __nv_bfloat16* kh, const __nv_bfloat16* kl,
        const __nv_bfloat16* vh, const __nv_bfloat16* vl,
        int m0, int buf, int tid)
{
    const int bo = buf * KVBUF;
    #pragma unroll
    for (int j = 0; j < 2; j++) {
        int idx = tid + j*256;          // 0..511
        int r = idx >> 3;               // row 0..63
        int o = (idx & 7) * 16;         // byte offset within 128B row
        cpasync16(smc + AS_KH + bo + r*SDB + o, (const char*)kh + ((size_t)(m0 + r))*128 + o);
        cpasync16(smc + AS_KL + bo + r*SDB + o, (const char*)kl + ((size_t)(m0 + r))*128 + o);
        cpasync16(smc + AS_VH + bo + r*SDB + o, (const char*)vh + ((size_t)r*MM + m0)*2 + o);
        cpasync16(smc + AS_VL + bo + r*SDB + o, (const char*)vl + ((size_t)r*MM + m0)*2 + o);
    }
}

__global__ __launch_bounds__(256)
void attn_hmma(const float* __restrict__ alibi)
{
    extern __shared__ char smc[];
    const int tid  = threadIdx.x;
    const int w    = tid >> 5;
    const int lane = tid & 31;
    const int g    = lane >> 2;
    const int t4   = lane & 3;
    const int bh   = blockIdx.y;
    const int n0   = blockIdx.x * 128;
    const int b    = bh >> 4, h = bh & 15;

    const __nv_bfloat16* qh = g_qhh + ((size_t)bh*NN + n0)*DD;
    const __nv_bfloat16* ql = g_qhl + ((size_t)bh*NN + n0)*DD;
    const __nv_bfloat16* kh = g_kh + (size_t)bh*MM*DD;
    const __nv_bfloat16* kl = g_kl + (size_t)bh*MM*DD;
    const __nv_bfloat16* vh = g_vh + (size_t)bh*DD*MM;
    const __nv_bfloat16* vl = g_vl + (size_t)bh*DD*MM;
    const float* ab   = alibi + ((size_t)(bh*NN) + n0)*MM;
    const float* mrow = g_maskbias + (size_t)b*MM;

    #pragma unroll
    for (int j = 0; j < 4; j++) {
        int idx = tid + j*256;
        int r = idx >> 3, o = (idx & 7) * 16;
        cpasync16(smc + AS_QH + r*SDB + o, (const char*)qh + (size_t)r*128 + o);
        cpasync16(smc + AS_QL + r*SDB + o, (const char*)ql + (size_t)r*128 + o);
    }
    attn_load_kv(smc, kh, kl, vh, vl, 0, 0, tid);
    CP_COMMIT();

    float oacc[8][4];
    #pragma unroll
    for (int nt = 0; nt < 8; nt++)
        #pragma unroll
        for (int i = 0; i < 4; i++) oacc[nt][i] = 0.0f;
    float lp0 = 0.0f, lp1 = 0.0f;

    const int qrow = w*16 + g;

    #pragma unroll 1
    for (int t = 0; t < MM/64; t++) {
        const int m0 = t * 64;
        const int buf = t & 1;

        CP_WAIT0();
        __syncthreads();
        if (t + 1 < MM/64) {
            attn_load_kv(smc, kh, kl, vh, vl, m0 + 64, buf ^ 1, tid);
            CP_COMMIT();
        }

        float2 a0r[8], a1r[8], mb[8];
        #pragma unroll
        for (int nt = 0; nt < 8; nt++) {
            const int mc = m0 + nt*8 + 2*t4;
            a0r[nt] = *(const float2*)&ab[(size_t)qrow*MM + mc];
            a1r[nt] = *(const float2*)&ab[(size_t)(qrow+8)*MM + mc];
            mb[nt]  = *(const float2*)&mrow[mc];
        }

        float sacc[8][4];
        #pragma unroll
        for (int nt = 0; nt < 8; nt++)
            #pragma unroll
            for (int i = 0; i < 4; i++) sacc[nt][i] = 0.0f;

        const char* kbh = smc + AS_KH + buf*KVBUF;
        const char* kbl = smc + AS_KL + buf*KVBUF;
        #pragma unroll
        for (int kt = 0; kt < 4; kt++) {
            const int abase = qrow*SDB + kt*32 + t4*4;
            unsigned ah[4], al[4];
            ah[0] = *(const unsigned*)(smc + AS_QH + abase);
            ah[1] = *(const unsigned*)(smc + AS_QH + abase + 8*SDB);
            ah[2] = *(const unsigned*)(smc + AS_QH + abase + 16);
            ah[3] = *(const unsigned*)(smc + AS_QH + abase + 8*SDB + 16);
            al[0] = *(const unsigned*)(smc + AS_QL + abase);
            al[1] = *(const unsigned*)(smc + AS_QL + abase + 8*SDB);
            al[2] = *(const unsigned*)(smc + AS_QL + abase + 16);
            al[3] = *(const unsigned*)(smc + AS_QL + abase + 8*SDB + 16);
            #pragma unroll
            for (int nt = 0; nt < 8; nt++) {
                const int bb = (nt*8 + g)*SDB + kt*32 + t4*4;
                unsigned bhf[2] = { *(const unsigned*)(kbh + bb),
                                    *(const unsigned*)(kbh + bb + 16) };
                unsigned blf[2] = { *(const unsigned*)(kbl + bb),
                                    *(const unsigned*)(kbl + bb + 16) };
                mma16816(sacc[nt], ah, bhf);
                mma16816(sacc[nt], ah, blf);
                mma16816(sacc[nt], al, bhf);
            }
        }

        unsigned ph0[8], ph1[8], pl0[8], pl1[8];
        #pragma unroll
        for (int nt = 0; nt < 8; nt++) {
            float p00 = __expf(fminf(sacc[nt][0] + a0r[nt].x + mb[nt].x, 60.0f));
            float p01 = __expf(fminf(sacc[nt][1] + a0r[nt].y + mb[nt].y, 60.0f));
            float p10 = __expf(fminf(sacc[nt][2] + a1r[nt].x + mb[nt].x, 60.0f));
            float p11 = __expf(fminf(sacc[nt][3] + a1r[nt].y + mb[nt].y, 60.0f));
            lp0 += p00 + p01;
            lp1 += p10 + p11;
            __nv_bfloat162 hh, ll;
            split2(p00, p01, hh, ll);
            ph0[nt] = *reinterpret_cast<unsigned*>(&hh);
            pl0[nt] = *reinterpret_cast<unsigned*>(&ll);
            split2(p10, p11, hh, ll);
            ph1[nt] = *reinterpret_cast<unsigned*>(&hh);
            pl1[nt] = *reinterpret_cast<unsigned*>(&ll);
        }

        const char* vbh = smc + AS_VH + buf*KVBUF;
        const char* vbl = smc + AS_VL + buf*KVBUF;
        #pragma unroll
        for (int kt = 0; kt < 4; kt++) {
            unsigned aH[4] = { ph0[2*kt], ph1[2*kt], ph0[2*kt+1], ph1[2*kt+1] };
            unsigned aL[4] = { pl0[2*kt], pl1[2*kt], pl0[2*kt+1], pl1[2*kt+1] };
            #pragma unroll
            for (int nt = 0; nt < 8; nt++) {
                const int bb = (nt*8 + g)*SDB + kt*32 + t4*4;
                unsigned bhf[2] = { *(const unsigned*)(vbh + bb),
                                    *(const unsigned*)(vbh + bb + 16) };
                unsigned blf[2] = { *(const unsigned*)(vbl + bb),
                                    *(const unsigned*)(vbl + bb + 16) };
                mma16816(oacc[nt], aH, bhf);
                mma16816(oacc[nt], aH, blf);
                mma16816(oacc[nt], aL, bhf);
            }
        }
    }

    lp0 += __shfl_xor_sync(0xFFFFFFFF, lp0, 1);
    lp0 += __shfl_xor_sync(0xFFFFFFFF, lp0, 2);
    lp1 += __shfl_xor_sync(0xFFFFFFFF, lp1, 1);
    lp1 += __shfl_xor_sync(0xFFFFFFFF, lp1, 2);
    const float li0 = 1.0f / lp0;
    const float li1 = 1.0f / lp1;

    // write normalized output split to g_xh/g_xl [b, n, h*64 + d]
    const size_t xo = ((size_t)b*NN + n0 + w*16)*CC + h*DD;
    #pragma unroll
    for (int nt = 0; nt < 8; nt++) {
        const int dc = nt*8 + 2*t4;
        __nv_bfloat162 hh, ll;
        split2(oacc[nt][0]*li0, oacc[nt][1]*li0, hh, ll);
        *(__nv_bfloat162*)&g_xh[xo + (size_t)g*CC + dc] = hh;
        *(__nv_bfloat162*)&g_xl[xo + (size_t)g*CC + dc] = ll;
        split2(oacc[nt][2]*li1, oacc[nt][3]*li1, hh, ll);
        *(__nv_bfloat162*)&g_xh[xo + (size_t)(g+8)*CC + dc] = hh;
        *(__nv_bfloat162*)&g_xl[xo + (size_t)(g+8)*CC + dc] = ll;
    }
}

// ---------------------------------------------------------------------------
extern "C" void kernel_launch(void* const* d_in, const int* in_sizes, int n_in,
                              void* d_out, int out_size)
{
    const float *q = nullptr, *kv = nullptr, *alibi = nullptr;
    const float *Wq = nullptr, *Wkv = nullptr, *Wproj = nullptr, *bproj = nullptr;
    const void  *maskp = nullptr;
    int wseen = 0;
    for (int i = 0; i < n_in; i++) {
        switch (in_sizes[i]) {
            case 2097152:  q     = (const float*)d_in[i]; break;           // (2,1024,1024)
            case 3145728:  kv    = (const float*)d_in[i]; break;           // (2,2048,768)
            case 67108864: alibi = (const float*)d_in[i]; break;           // (2,16,1024,2048)
            case 4096:     maskp = d_in[i]; break;                          // (2,2048) bool
            case 1572864:  Wkv   = (const float*)d_in[i]; break;           // (2048,768)
            case 1024:     bproj = (const float*)d_in[i]; break;           // (1024,)
            case 1048576:                                                   // Wq then Wproj
                if (wseen++ == 0) Wq = (const float*)d_in[i];
                else              Wproj = (const float*)d_in[i];
                break;
            default: break;
        }
    }
    float* out = (float*)d_out;
    (void)out_size;

    cudaFuncSetAttribute(attn_hmma,
                         cudaFuncAttributeMaxDynamicSharedMemorySize, ATT_SMEM_BYTES);

    mask_prep<<<1, 256>>>((const unsigned char*)maskp);

    // One fused prep kernel: split all GEMM operands to bf16 hi/lo
    split_all<<<1024, 256>>>((const float4*)q, (const float4*)kv,
                             (const float4*)Wq, (const float4*)Wkv,
                             (const float4*)Wproj);

    // Fused Q + KV projections (640 CTAs, 2 CTAs/SM)
    qkv_gemm<<<640, 256>>>();
    // Fused HMMA attention (outputs pre-split g_xh/g_xl)
    attn_hmma<<<dim3(NN/128, BB*HH), 256, ATT_SMEM_BYTES>>>(alibi);
    // Output projection
    oproj_gemm<<<128, 256>>>(bproj, out);
}